// round 1
// baseline (speedup 1.0000x reference)
#include <cuda_runtime.h>
#include <math.h>

#define BB 32
#define SS 1024
#define HDIM 256
#define DD2 512

// ---------------- device scratch (static: no allocations allowed) ----------------
__device__ float g_bufA[BB*SS*DD2];   // layer0 output [b][s][512]
__device__ float g_bufB[BB*SS*DD2];   // layer1 output [b][s][512]
__device__ float g_ctx [BB*SS*DD2];   // attention context
__device__ float g_hx  [2*2*BB*HDIM]; // [dir][parity][b][j] h exchange
__device__ unsigned int g_cnt[2];     // per-direction barrier counters
__device__ float g_E  [BB*SS];
__device__ float g_DEN[BB*SS];

__device__ __forceinline__ float sigf(float x){ return 1.0f/(1.0f+expf(-x)); }

// ---------------- init: zero h-exchange + counters ----------------
__global__ void init_kernel(){
  int i = blockIdx.x*blockDim.x + threadIdx.x;
  if (i < 2) g_cnt[i] = 0u;
  if (i < 2*2*BB*HDIM) g_hx[i] = 0.0f;
}

// ---------------- persistent bidirectional LSTM layer ----------------
// grid = 128 blocks: dir = blk>>6 (0=fwd,1=bwd), 64 blocks per dir, each owns 4 hidden units.
// thread layout: r = tid&15 (gate row: g*4+jl), kc = tid>>4 (k-chunk). Weights register-resident.
template<int K, int DIN>
__global__ void __launch_bounds__(256,1) lstm_layer_kernel(
    const float* __restrict__ in,      // [B,S,DIN]
    const float* __restrict__ wih_f, const float* __restrict__ whh_f, const float* __restrict__ bias_f,
    const float* __restrict__ wih_b, const float* __restrict__ whh_b, const float* __restrict__ bias_b,
    float* __restrict__ out)           // [B,S,512]
{
  constexpr int KC = K/16;
  extern __shared__ float sm[];
  float* vbuf = sm;                 // [32][K]   combined [h | x_s]
  float* part = vbuf + 32*K;        // [32][257] k-chunk partials (padded)
  float* gsm  = part + 32*257;      // [16][33]  reduced gates (padded)
  float* csm  = gsm + 16*33;        // [4][32]   cell state
  float* bsm  = csm + 128;          // [16]      biases

  const int tid = threadIdx.x;
  const int blk = blockIdx.x;
  const int dir = blk >> 6;
  const int j0  = (blk & 63) * 4;
  const int r   = tid & 15;
  const int kc  = tid >> 4;
  const int row = (r >> 2)*HDIM + j0 + (r & 3);   // gate-major row in [0,4H)

  const float* wih  = dir ? wih_b  : wih_f;
  const float* whh  = dir ? whh_b  : whh_f;
  const float* bias = dir ? bias_b : bias_f;

  // load this thread's weight chunk into registers (combined [w_hh | w_ih] row)
  float wreg[KC];
  #pragma unroll
  for (int q=0;q<KC;q++){
    int kk = kc*KC + q;
    wreg[q] = (kk < HDIM) ? whh[row*HDIM + kk] : wih[row*DIN + (kk - HDIM)];
  }
  if (tid < 128) csm[tid] = 0.0f;
  if (tid < 16)  bsm[tid] = bias[(tid>>2)*HDIM + j0 + (tid&3)];
  __syncthreads();

  unsigned int* cnt = &g_cnt[dir];
  float* hx0 = g_hx + dir*(2*BB*HDIM);

  for (int s=0;s<SS;s++){
    const int par   = s & 1;
    const int s_eff = dir ? (SS-1-s) : s;

    // load v = [h_prev | x_{s_eff}] into smem (h via L2, bypassing stale L1)
    const float4* hsrc = (const float4*)(hx0 + par*(BB*HDIM));
    #pragma unroll
    for (int idx=tid; idx < BB*HDIM/4; idx += 256){
      float4 hv = __ldcg(hsrc + idx);
      int b = idx >> 6, c4 = idx & 63;
      *(float4*)&vbuf[b*K + c4*4] = hv;
    }
    for (int idx=tid; idx < BB*(DIN/4); idx += 256){
      int b = idx / (DIN/4), c4 = idx % (DIN/4);
      float4 xv = *(const float4*)&in[(size_t)(b*SS + s_eff)*DIN + c4*4];
      *(float4*)&vbuf[b*K + HDIM + c4*4] = xv;
    }
    __syncthreads();

    // partial dot products: 16 lanes share each v address (smem broadcast)
    #pragma unroll 2
    for (int b=0;b<BB;b++){
      const float4* vp = (const float4*)&vbuf[b*K + kc*KC];
      float a0=0.f,a1=0.f,a2=0.f,a3=0.f;
      #pragma unroll
      for (int q=0;q<KC/4;q++){
        float4 v4 = vp[q];
        a0 += wreg[4*q+0]*v4.x;
        a1 += wreg[4*q+1]*v4.y;
        a2 += wreg[4*q+2]*v4.z;
        a3 += wreg[4*q+3]*v4.w;
      }
      part[b*257 + tid] = (a0+a1)+(a2+a3);   // tid == kc*16 + r
    }
    __syncthreads();

    // reduce across the 16 k-chunks, add bias
    #pragma unroll
    for (int oo=0;oo<2;oo++){
      int o  = tid + oo*256;
      int rr = o >> 5, b = o & 31;
      float a = bsm[rr];
      #pragma unroll
      for (int q=0;q<16;q++) a += part[b*257 + q*16 + rr];
      gsm[rr*33 + b] = a;
    }
    __syncthreads();

    // cell update for this block's 4 hidden units x 32 batches
    if (tid < 128){
      int jj = tid >> 5, b = tid & 31;
      float gi = gsm[(0*4+jj)*33 + b];
      float gf = gsm[(1*4+jj)*33 + b];
      float gg = gsm[(2*4+jj)*33 + b];
      float go = gsm[(3*4+jj)*33 + b];
      float c = csm[jj*32 + b];
      c = sigf(gf)*c + sigf(gi)*tanhf(gg);
      float h = sigf(go)*tanhf(c);
      csm[jj*32 + b] = c;
      int j = j0 + jj;
      __stcg(&hx0[((s+1)&1)*(BB*HDIM) + b*HDIM + j], h);
      out[(size_t)(b*SS + s_eff)*DD2 + dir*HDIM + j] = h;
    }
    __threadfence();
    __syncthreads();

    // per-direction inter-block barrier (monotonic counter; all 128 blocks co-resident)
    if (tid == 0){
      atomicAdd(cnt, 1u);
      unsigned int target = 64u*(unsigned int)(s+1);
      while (*((volatile unsigned int*)cnt) < target) { }
    }
    __syncthreads();
  }
}

// ---------------- attention scores: e and cumulative denominator ----------------
__global__ void attn_kernel(const float* __restrict__ aw, const float* __restrict__ ab){
  __shared__ __align__(16) float swa[DD2];
  __shared__ float ssm[SS];
  __shared__ float red[256];
  int b = blockIdx.x, tid = threadIdx.x;
  for (int i=tid;i<DD2;i+=256) swa[i] = aw[i];
  __syncthreads();
  float ab0 = ab[0];
  const float4* wp = (const float4*)swa;
  for (int t=tid;t<SS;t+=256){
    const float4* hp = (const float4*)&g_bufB[(size_t)(b*SS+t)*DD2];
    float a0=0.f,a1=0.f,a2=0.f,a3=0.f;
    #pragma unroll 8
    for (int q=0;q<DD2/4;q++){
      float4 h4 = hp[q]; float4 w4 = wp[q];
      a0 += h4.x*w4.x; a1 += h4.y*w4.y; a2 += h4.z*w4.z; a3 += h4.w*w4.w;
    }
    ssm[t] = (a0+a1)+(a2+a3) + ab0;
  }
  __syncthreads();
  float m = -1e30f;
  for (int t=tid;t<SS;t+=256) m = fmaxf(m, ssm[t]);
  red[tid] = m; __syncthreads();
  for (int off=128; off>0; off>>=1){
    if (tid<off) red[tid] = fmaxf(red[tid], red[tid+off]);
    __syncthreads();
  }
  float smax = red[0];
  for (int t=tid;t<SS;t+=256){
    float e = expf(ssm[t]-smax);
    ssm[t] = e;
    g_E[b*SS+t] = e;
  }
  __syncthreads();
  if (tid==0){
    float run=0.f;
    for (int t=0;t<SS;t++){ run += ssm[t]; g_DEN[b*SS+t] = run; }
  }
}

// ---------------- cumulative context: thread = (b, j), coalesced over j ----------------
__global__ void ctx_kernel(){
  int gid = blockIdx.x*blockDim.x + threadIdx.x;   // 16384 threads
  int b = gid >> 9, j = gid & 511;
  const float* hp = g_bufB + (size_t)b*SS*DD2 + j;
  float*       cp = g_ctx  + (size_t)b*SS*DD2 + j;
  const float* Ep = g_E   + b*SS;
  const float* Dp = g_DEN + b*SS;
  float run = 0.f;
  for (int t=0;t<SS;t++){
    run += Ep[t]*hp[(size_t)t*DD2];
    cp[(size_t)t*DD2] = run / Dp[t];
  }
}

// ---------------- head projection: [32768,512] @ [128,512]^T + bias ----------------
__global__ void head_kernel(const float* __restrict__ hw, const float* __restrict__ hb,
                            float* __restrict__ out){
  __shared__ float As[32][132];
  __shared__ float Bs[32][132];
  int tid = threadIdx.x;
  int row0 = blockIdx.x * 128;
  int tx = tid & 15, ty = tid >> 4;
  float acc[8][8];
  #pragma unroll
  for (int i=0;i<8;i++)
    #pragma unroll
    for (int j=0;j<8;j++) acc[i][j] = 0.f;

  for (int kt=0; kt<512; kt+=32){
    #pragma unroll
    for (int l=0;l<4;l++){
      int idx = tid + l*256;
      int rr = idx >> 3, c4 = idx & 7;
      float4 v = *(const float4*)&g_ctx[(size_t)(row0+rr)*512 + kt + c4*4];
      As[c4*4+0][rr]=v.x; As[c4*4+1][rr]=v.y; As[c4*4+2][rr]=v.z; As[c4*4+3][rr]=v.w;
    }
    #pragma unroll
    for (int l=0;l<4;l++){
      int idx = tid + l*256;
      int rr = idx >> 3, c4 = idx & 7;
      float4 v = *(const float4*)&hw[(size_t)rr*512 + kt + c4*4];
      Bs[c4*4+0][rr]=v.x; Bs[c4*4+1][rr]=v.y; Bs[c4*4+2][rr]=v.z; Bs[c4*4+3][rr]=v.w;
    }
    __syncthreads();
    #pragma unroll
    for (int kk=0;kk<32;kk++){
      float a[8], bb[8];
      #pragma unroll
      for (int i=0;i<8;i++) a[i]  = As[kk][ty*8+i];
      #pragma unroll
      for (int j=0;j<8;j++) bb[j] = Bs[kk][tx*8+j];
      #pragma unroll
      for (int i=0;i<8;i++)
        #pragma unroll
        for (int j=0;j<8;j++) acc[i][j] += a[i]*bb[j];
    }
    __syncthreads();
  }
  #pragma unroll
  for (int i=0;i<8;i++){
    int rr = row0 + ty*8 + i;
    #pragma unroll
    for (int j=0;j<8;j++){
      int n = tx*8 + j;
      out[(size_t)rr*128 + n] = acc[i][j] + hb[n];
    }
  }
}

// ---------------- launch ----------------
extern "C" void kernel_launch(void* const* d_in, const int* in_sizes, int n_in,
                              void* d_out, int out_size){
  const float* x     = (const float*)d_in[0];
  const float* wih0f = (const float*)d_in[1];
  const float* whh0f = (const float*)d_in[2];
  const float* b0f   = (const float*)d_in[3];
  const float* wih0b = (const float*)d_in[4];
  const float* whh0b = (const float*)d_in[5];
  const float* b0b   = (const float*)d_in[6];
  const float* wih1f = (const float*)d_in[7];
  const float* whh1f = (const float*)d_in[8];
  const float* b1f   = (const float*)d_in[9];
  const float* wih1b = (const float*)d_in[10];
  const float* whh1b = (const float*)d_in[11];
  const float* b1b   = (const float*)d_in[12];
  const float* attw  = (const float*)d_in[13];
  const float* attb  = (const float*)d_in[14];
  const float* hw    = (const float*)d_in[15];
  const float* hb    = (const float*)d_in[16];
  float* out = (float*)d_out;

  void* pA = 0; void* pB = 0;
  cudaGetSymbolAddress(&pA, g_bufA);
  cudaGetSymbolAddress(&pB, g_bufB);

  const int SMEM0 = (32*384 + 32*257 + 16*33 + 128 + 16)*4;  // ~84.7 KB
  const int SMEM1 = (32*768 + 32*257 + 16*33 + 128 + 16)*4;  // ~133.9 KB
  cudaFuncSetAttribute(lstm_layer_kernel<384,128>, cudaFuncAttributeMaxDynamicSharedMemorySize, SMEM0);
  cudaFuncSetAttribute(lstm_layer_kernel<768,512>, cudaFuncAttributeMaxDynamicSharedMemorySize, SMEM1);

  init_kernel<<<256,256>>>();
  lstm_layer_kernel<384,128><<<128,256,SMEM0>>>(x, wih0f, whh0f, b0f, wih0b, whh0b, b0b, (float*)pA);
  init_kernel<<<256,256>>>();
  lstm_layer_kernel<768,512><<<128,256,SMEM1>>>((const float*)pA, wih1f, whh1f, b1f, wih1b, whh1b, b1b, (float*)pB);
  attn_kernel<<<32,256>>>(attw, attb);
  ctx_kernel<<<64,256>>>();
  head_kernel<<<256,256>>>(hw, hb, out);
}

// round 2
// speedup vs baseline: 1.4010x; 1.4010x over previous
#include <cuda_runtime.h>
#include <math.h>

#define BB 32
#define SS 1024
#define HDIM 256
#define DD2 512
#define GATES 1024   // 4*H

// ---------------- device scratch ----------------
__device__ float g_bufA[BB*SS*DD2];            // layer0 output [b][s][512]
__device__ float g_bufB[BB*SS*DD2];            // layer1 output [b][s][512]
__device__ float g_ctx [BB*SS*DD2];            // attention context
__device__ float g_xp  [2u*SS*GATES*BB];       // [dir][s][row][b]  (268MB)
__device__ float g_hx  [2*2*BB*HDIM];          // [dir][parity][b][j]
__device__ unsigned int g_cnt[2];              // per-direction barrier counters
__device__ float g_E  [BB*SS];
__device__ float g_DEN[BB*SS];

__device__ __forceinline__ float sigf(float x){ return 1.0f/(1.0f+expf(-x)); }

// ---------------- init ----------------
__global__ void init_kernel(){
  int i = blockIdx.x*blockDim.x + threadIdx.x;
  if (i < 2) g_cnt[i] = 0u;
  if (i < 2*2*BB*HDIM) g_hx[i] = 0.0f;
}

// ---------------- XP GEMM: xp[dir][s][row][b] = sum_k W[row,k]*X[b,s,k] + bias[row] ----------------
// grid: (8 row-tiles, 256 s-groups, 2 dirs); block 256 threads; C tile = 128 rows x (4 s x 32 b)
template<int K>
__global__ void __launch_bounds__(256,2) xp_gemm_kernel(
    const float* __restrict__ Wf, const float* __restrict__ Wb,
    const float* __restrict__ bf, const float* __restrict__ bb,
    const float* __restrict__ X)   // [b][s][K]
{
  __shared__ float As[32][132];
  __shared__ float Bs[32][132];
  const int tid  = threadIdx.x;
  const int row0 = blockIdx.x * 128;
  const int s0   = blockIdx.y * 4;
  const int dir  = blockIdx.z;
  const float* W    = dir ? Wb : Wf;
  const float* bias = dir ? bb : bf;
  float* xp = g_xp + (size_t)dir * (SS*(size_t)GATES*BB);

  const int tx = tid & 15, ty = tid >> 4;
  float acc[8][8];
  #pragma unroll
  for (int i=0;i<8;i++)
    #pragma unroll
    for (int j=0;j<8;j++) acc[i][j]=0.f;

  for (int kt = 0; kt < K; kt += 32){
    #pragma unroll
    for (int l=0;l<4;l++){
      int idx = tid + l*256;
      int rr = idx >> 3, kq = idx & 7;
      float4 v = *(const float4*)&W[(size_t)(row0+rr)*K + kt + kq*4];
      As[kq*4+0][rr]=v.x; As[kq*4+1][rr]=v.y; As[kq*4+2][rr]=v.z; As[kq*4+3][rr]=v.w;
    }
    #pragma unroll
    for (int l=0;l<4;l++){
      int idx = tid + l*256;
      int c = idx >> 3, kq = idx & 7;
      int b = c & 31, sg = c >> 5;
      float4 v = *(const float4*)&X[(size_t)(b*SS + s0+sg)*K + kt + kq*4];
      Bs[kq*4+0][c]=v.x; Bs[kq*4+1][c]=v.y; Bs[kq*4+2][c]=v.z; Bs[kq*4+3][c]=v.w;
    }
    __syncthreads();
    #pragma unroll
    for (int kk=0;kk<32;kk++){
      float a[8], bv[8];
      #pragma unroll
      for (int i=0;i<8;i++) a[i]  = As[kk][ty*8+i];
      #pragma unroll
      for (int j=0;j<8;j++) bv[j] = Bs[kk][tx*8+j];
      #pragma unroll
      for (int i=0;i<8;i++)
        #pragma unroll
        for (int j=0;j<8;j++) acc[i][j] += a[i]*bv[j];
    }
    __syncthreads();
  }
  // store: col = tx*8+j -> sg = tx>>2, b = (tx&3)*8 + j
  const int sgb = tx >> 2;
  const int b0  = (tx & 3) * 8;
  const size_t sbase = (size_t)(s0 + sgb) * (GATES*BB);
  #pragma unroll
  for (int i=0;i<8;i++){
    int row = row0 + ty*8 + i;
    float bvv = __ldg(&bias[row]);
    float4 o0, o1;
    o0.x=acc[i][0]+bvv; o0.y=acc[i][1]+bvv; o0.z=acc[i][2]+bvv; o0.w=acc[i][3]+bvv;
    o1.x=acc[i][4]+bvv; o1.y=acc[i][5]+bvv; o1.z=acc[i][6]+bvv; o1.w=acc[i][7]+bvv;
    *(float4*)&xp[sbase + (size_t)row*BB + b0    ] = o0;
    *(float4*)&xp[sbase + (size_t)row*BB + b0 + 4] = o1;
  }
}

// ---------------- sequential recurrence: gates = xp + h @ whh^T ----------------
// 128 blocks x 512 threads, 1/SM single wave. dir = blk>>6, 4 hidden units per block.
// dot role:   rW = tid&15 (gate row), kc = tid>>4 (32 chunks of 8), 8 weight regs.
// reduce role: rR = tid>>5 (gate row), bR = tid&31.
__global__ void __launch_bounds__(512,1) lstm_seq_kernel(
    const float* __restrict__ whh_f, const float* __restrict__ whh_b,
    const float* __restrict__ xp_base,   // g_xp
    float* __restrict__ out)             // [b][s][512]
{
  extern __shared__ float sm[];
  float* vbuf = sm;               // [32][256] h values
  float* part = vbuf + 32*256;    // [32*529] partials: part[b*529 + rW*33 + kc]
  float* gsm  = part + 32*529;    // [16][33]
  float* csm  = gsm + 16*33;      // [4][32]

  const int tid = threadIdx.x;
  const int blk = blockIdx.x;
  const int dir = blk >> 6;
  const int j0  = (blk & 63) * 4;

  const int rW   = tid & 15;
  const int kc   = tid >> 4;          // 0..31
  const int rowW = (rW >> 2)*HDIM + j0 + (rW & 3);
  const float* whh = dir ? whh_b : whh_f;
  float wreg[8];
  #pragma unroll
  for (int q=0;q<8;q++) wreg[q] = whh[(size_t)rowW*HDIM + kc*8 + q];

  const int rR = tid >> 5;            // 0..15
  const int bR = tid & 31;
  const int rowR = (rR >> 2)*HDIM + j0 + (rR & 3);
  const float* xp = xp_base + (size_t)dir*(SS*(size_t)GATES*BB) + (size_t)rowR*BB + bR;

  if (tid < 128) csm[tid] = 0.0f;
  __syncthreads();

  unsigned int* cnt = &g_cnt[dir];
  float* hx0 = g_hx + dir*(2*BB*HDIM);

  for (int s=0;s<SS;s++){
    const int par   = s & 1;
    const int s_eff = dir ? (SS-1-s) : s;

    // prefetch this thread's xp value (coalesced 128B/warp); consumed after dot phase
    float xpv = __ldg(xp + (size_t)s_eff*(GATES*BB));

    // load h_prev into smem (L2, bypass stale L1)
    const float4* hsrc = (const float4*)(hx0 + par*(BB*HDIM));
    #pragma unroll
    for (int l=0;l<4;l++){
      int idx = tid + l*512;          // 2048 float4 total
      float4 hv = __ldcg(hsrc + idx);
      *(float4*)&vbuf[idx*4] = hv;
    }
    __syncthreads();

    // dot: each thread, for each batch, 8-wide chunk of the row (smem broadcast reads)
    #pragma unroll 2
    for (int b=0;b<BB;b++){
      const float4* vp = (const float4*)&vbuf[b*HDIM + kc*8];
      float4 v0 = vp[0], v1 = vp[1];
      float a0 = wreg[0]*v0.x;  a0 = fmaf(wreg[1],v0.y,a0);
      a0 = fmaf(wreg[2],v0.z,a0); a0 = fmaf(wreg[3],v0.w,a0);
      float a1 = wreg[4]*v1.x;  a1 = fmaf(wreg[5],v1.y,a1);
      a1 = fmaf(wreg[6],v1.z,a1); a1 = fmaf(wreg[7],v1.w,a1);
      part[b*529 + rW*33 + kc] = a0 + a1;
    }
    __syncthreads();

    // reduce 32 chunks + xp (conflict-free: 529 mod 32 = 17, odd)
    {
      const float* pp = &part[bR*529 + rR*33];
      float c0 = xpv, c1 = 0.f, c2 = 0.f, c3 = 0.f;
      #pragma unroll
      for (int q=0;q<32;q+=4){ c0 += pp[q]; c1 += pp[q+1]; c2 += pp[q+2]; c3 += pp[q+3]; }
      gsm[rR*33 + bR] = (c0+c1)+(c2+c3);
    }
    __syncthreads();

    // cell update: 4 units x 32 batches
    if (tid < 128){
      int jj = tid >> 5, b = tid & 31;
      float gi = gsm[(0*4+jj)*33 + b];
      float gf = gsm[(1*4+jj)*33 + b];
      float gg = gsm[(2*4+jj)*33 + b];
      float go = gsm[(3*4+jj)*33 + b];
      float c = csm[jj*32 + b];
      c = sigf(gf)*c + sigf(gi)*tanhf(gg);
      float h = sigf(go)*tanhf(c);
      csm[jj*32 + b] = c;
      int j = j0 + jj;
      __stcg(&hx0[((s+1)&1)*(BB*HDIM) + b*HDIM + j], h);
      out[(size_t)(b*SS + s_eff)*DD2 + dir*HDIM + j] = h;
    }
    __threadfence();
    __syncthreads();

    // per-direction inter-block barrier (64 blocks/dir, all resident)
    if (tid == 0){
      atomicAdd(cnt, 1u);
      unsigned int target = 64u*(unsigned int)(s+1);
      while (*((volatile unsigned int*)cnt) < target) { }
    }
    __syncthreads();
  }
}

// ---------------- attention scores ----------------
__global__ void attn_kernel(const float* __restrict__ aw, const float* __restrict__ ab){
  __shared__ __align__(16) float swa[DD2];
  __shared__ float ssm[SS];
  __shared__ float red[256];
  int b = blockIdx.x, tid = threadIdx.x;
  for (int i=tid;i<DD2;i+=256) swa[i] = aw[i];
  __syncthreads();
  float ab0 = ab[0];
  const float4* wp = (const float4*)swa;
  for (int t=tid;t<SS;t+=256){
    const float4* hp = (const float4*)&g_bufB[(size_t)(b*SS+t)*DD2];
    float a0=0.f,a1=0.f,a2=0.f,a3=0.f;
    #pragma unroll 8
    for (int q=0;q<DD2/4;q++){
      float4 h4 = hp[q]; float4 w4 = wp[q];
      a0 += h4.x*w4.x; a1 += h4.y*w4.y; a2 += h4.z*w4.z; a3 += h4.w*w4.w;
    }
    ssm[t] = (a0+a1)+(a2+a3) + ab0;
  }
  __syncthreads();
  float m = -1e30f;
  for (int t=tid;t<SS;t+=256) m = fmaxf(m, ssm[t]);
  red[tid] = m; __syncthreads();
  for (int off=128; off>0; off>>=1){
    if (tid<off) red[tid] = fmaxf(red[tid], red[tid+off]);
    __syncthreads();
  }
  float smax = red[0];
  for (int t=tid;t<SS;t+=256){
    float e = expf(ssm[t]-smax);
    ssm[t] = e;
    g_E[b*SS+t] = e;
  }
  __syncthreads();
  if (tid==0){
    float run=0.f;
    for (int t=0;t<SS;t++){ run += ssm[t]; g_DEN[b*SS+t] = run; }
  }
}

// ---------------- cumulative context ----------------
__global__ void ctx_kernel(){
  int gid = blockIdx.x*blockDim.x + threadIdx.x;   // 16384 threads
  int b = gid >> 9, j = gid & 511;
  const float* hp = g_bufB + (size_t)b*SS*DD2 + j;
  float*       cp = g_ctx  + (size_t)b*SS*DD2 + j;
  const float* Ep = g_E   + b*SS;
  const float* Dp = g_DEN + b*SS;
  float run = 0.f;
  for (int t=0;t<SS;t++){
    run += Ep[t]*hp[(size_t)t*DD2];
    cp[(size_t)t*DD2] = run / Dp[t];
  }
}

// ---------------- head projection: [32768,512] @ [128,512]^T + bias ----------------
__global__ void head_kernel(const float* __restrict__ hw, const float* __restrict__ hb,
                            float* __restrict__ out){
  __shared__ float As[32][132];
  __shared__ float Bs[32][132];
  int tid = threadIdx.x;
  int row0 = blockIdx.x * 128;
  int tx = tid & 15, ty = tid >> 4;
  float acc[8][8];
  #pragma unroll
  for (int i=0;i<8;i++)
    #pragma unroll
    for (int j=0;j<8;j++) acc[i][j] = 0.f;

  for (int kt=0; kt<512; kt+=32){
    #pragma unroll
    for (int l=0;l<4;l++){
      int idx = tid + l*256;
      int rr = idx >> 3, c4 = idx & 7;
      float4 v = *(const float4*)&g_ctx[(size_t)(row0+rr)*512 + kt + c4*4];
      As[c4*4+0][rr]=v.x; As[c4*4+1][rr]=v.y; As[c4*4+2][rr]=v.z; As[c4*4+3][rr]=v.w;
    }
    #pragma unroll
    for (int l=0;l<4;l++){
      int idx = tid + l*256;
      int rr = idx >> 3, c4 = idx & 7;
      float4 v = *(const float4*)&hw[(size_t)rr*512 + kt + c4*4];
      Bs[c4*4+0][rr]=v.x; Bs[c4*4+1][rr]=v.y; Bs[c4*4+2][rr]=v.z; Bs[c4*4+3][rr]=v.w;
    }
    __syncthreads();
    #pragma unroll
    for (int kk=0;kk<32;kk++){
      float a[8], bb[8];
      #pragma unroll
      for (int i=0;i<8;i++) a[i]  = As[kk][ty*8+i];
      #pragma unroll
      for (int j=0;j<8;j++) bb[j] = Bs[kk][tx*8+j];
      #pragma unroll
      for (int i=0;i<8;i++)
        #pragma unroll
        for (int j=0;j<8;j++) acc[i][j] += a[i]*bb[j];
    }
    __syncthreads();
  }
  #pragma unroll
  for (int i=0;i<8;i++){
    int rr = row0 + ty*8 + i;
    #pragma unroll
    for (int j=0;j<8;j++){
      int n = tx*8 + j;
      out[(size_t)rr*128 + n] = acc[i][j] + hb[n];
    }
  }
}

// ---------------- launch ----------------
extern "C" void kernel_launch(void* const* d_in, const int* in_sizes, int n_in,
                              void* d_out, int out_size){
  const float* x     = (const float*)d_in[0];
  const float* wih0f = (const float*)d_in[1];
  const float* whh0f = (const float*)d_in[2];
  const float* b0f   = (const float*)d_in[3];
  const float* wih0b = (const float*)d_in[4];
  const float* whh0b = (const float*)d_in[5];
  const float* b0b   = (const float*)d_in[6];
  const float* wih1f = (const float*)d_in[7];
  const float* whh1f = (const float*)d_in[8];
  const float* b1f   = (const float*)d_in[9];
  const float* wih1b = (const float*)d_in[10];
  const float* whh1b = (const float*)d_in[11];
  const float* b1b   = (const float*)d_in[12];
  const float* attw  = (const float*)d_in[13];
  const float* attb  = (const float*)d_in[14];
  const float* hw    = (const float*)d_in[15];
  const float* hb    = (const float*)d_in[16];
  float* out = (float*)d_out;

  void* pA = 0; void* pB = 0; void* pXP = 0;
  cudaGetSymbolAddress(&pA, g_bufA);
  cudaGetSymbolAddress(&pB, g_bufB);
  cudaGetSymbolAddress(&pXP, g_xp);

  const int SEQ_SMEM = (32*256 + 32*529 + 16*33 + 128)*4;   // 103104 B
  cudaFuncSetAttribute(lstm_seq_kernel, cudaFuncAttributeMaxDynamicSharedMemorySize, SEQ_SMEM);

  dim3 ggrid(8, 256, 2);

  // layer 0
  init_kernel<<<256,256>>>();
  xp_gemm_kernel<128><<<ggrid,256>>>(wih0f, wih0b, b0f, b0b, x);
  lstm_seq_kernel<<<128,512,SEQ_SMEM>>>(whh0f, whh0b, (const float*)pXP, (float*)pA);

  // layer 1
  init_kernel<<<256,256>>>();
  xp_gemm_kernel<512><<<ggrid,256>>>(wih1f, wih1b, b1f, b1b, (const float*)pA);
  lstm_seq_kernel<<<128,512,SEQ_SMEM>>>(whh1f, whh1b, (const float*)pXP, (float*)pB);

  // epilogue
  attn_kernel<<<32,256>>>(attw, attb);
  ctx_kernel<<<64,256>>>();
  head_kernel<<<256,256>>>(hw, hb, out);
}